// round 16
// baseline (speedup 1.0000x reference)
#include <cuda_runtime.h>
#include <cstdint>

// CarryLSTMModel: B=8192, T=1024, D=16, H=16 (4H=64 gates, order i,f,g,o)
// fp16 tensor-core variant: mma.sync.m16n8k16.f32.f16.f16.f32.
//   1 warp = 8 batch elements (rows 8-15 of each mma duplicate rows 0-7;
//   outputs ignored). 16 mmas/warp-step (8 gate-groups x {x-mma, h-mma})
//   -- HALF of R15's 32: per-warp mma dispatch was the binder.
//   fp16 mantissa (10 bit) == tf32 -> accuracy preserved (~1e-4).
//   Bias enters as C of the x-mma. Weights pre-scaled (0.5 i/f/o, 1 g):
//   sig(z)=0.5+0.5*tanh(z/2) via MUFU.TANH; gates of (e,j) on one lane.
//   x/h kept fp32 in smem, converted to f16x2 on load (LDS.64 + cvt).
//   RS=24 float row stride: LDS.64 pattern conflict-free per 16-lane phase.
//   x via 4-slot cp.async ring (distance 2, wait_group 1); h double-buffered.

#define NB 8192
#define NT 1024
#define ND 16
#define NG 64
#define RS 24                 // padded row stride (floats)
#define SLOT_B (8 * RS * 4)   // 768 bytes per 8x16 fp32 tile

typedef unsigned int u32;

__device__ __forceinline__ u32 smem_u32(const void* p) {
    return (u32)__cvta_generic_to_shared(p);
}
__device__ __forceinline__ float tanhap(float x) {
    float r; asm("tanh.approx.f32 %0, %1;" : "=f"(r) : "f"(x)); return r;
}
__device__ __forceinline__ float ex2f(float x) {
    float r; asm("ex2.approx.f32 %0, %1;" : "=f"(r) : "f"(x)); return r;
}
__device__ __forceinline__ float rcpf(float x) {
    float r; asm("rcp.approx.f32 %0, %1;" : "=f"(r) : "f"(x)); return r;
}
// pack two f32 -> f16x2 (lo = first arg)
__device__ __forceinline__ u32 pkh2(float lo, float hi) {
    u32 r; asm("cvt.rn.f16x2.f32 %0, %1, %2;" : "=r"(r) : "f"(hi), "f"(lo)); return r;
}
__device__ __forceinline__ void lds64(u32 a, float& x, float& y) {
    asm volatile("ld.shared.v2.f32 {%0, %1}, [%2];" : "=f"(x), "=f"(y) : "r"(a));
}
__device__ __forceinline__ void sts64(u32 a, float x, float y) {
    asm volatile("st.shared.v2.f32 [%0], {%1, %2};" :: "r"(a), "f"(x), "f"(y) : "memory");
}
__device__ __forceinline__ void cp16(u32 d, const float* s) {
    asm volatile("cp.async.ca.shared.global [%0], [%1], 16;" :: "r"(d), "l"(s) : "memory");
}
__device__ __forceinline__ void cp_commit() {
    asm volatile("cp.async.commit_group;" ::: "memory");
}
// D = A(f16 m16k16) @ B(f16 k16n8) + C(f32)
__device__ __forceinline__ void mma16(float& d0, float& d1, float& d2, float& d3,
                                      u32 a0, u32 a1, u32 a2, u32 a3,
                                      u32 b0, u32 b1,
                                      float c0, float c1, float c2, float c3)
{
    asm volatile("mma.sync.aligned.m16n8k16.row.col.f32.f16.f16.f32 "
        "{%0,%1,%2,%3}, {%4,%5,%6,%7}, {%8,%9}, {%10,%11,%12,%13};"
        : "=f"(d0), "=f"(d1), "=f"(d2), "=f"(d3)
        : "r"(a0), "r"(a1), "r"(a2), "r"(a3), "r"(b0), "r"(b1),
          "f"(c0), "f"(c1), "f"(c2), "f"(c3));
}

__global__ __launch_bounds__(128)
void lstm_mma_kernel(const float* __restrict__ x,
                     const float* __restrict__ Wi,
                     const float* __restrict__ Wh,
                     const float* __restrict__ bias,
                     const float* __restrict__ Wd,
                     const float* __restrict__ bd,
                     float* __restrict__ out)
{
    __shared__ __align__(16) float xsm[4][4][8 * RS];   // [warp][slot] x ring
    __shared__ __align__(16) float hsm[4][2][8 * RS];   // [warp][buf]  h

    const int wib  = threadIdx.x >> 5;
    const int lane = threadIdx.x & 31;
    const int gid  = lane >> 2;      // elem row (0..7)
    const int tig  = lane & 3;       // thread in group
    const int e0   = blockIdx.x * 32 + wib * 8;   // warp's 8 elements

    // ---- B fragments (f16x2, pre-scaled) + bias C-init ----
    // group g covers gate cols 8g..8g+7; lane's col n = 8g+gid.
    // b0: k = {2tig, 2tig+1}; b1: k = {2tig+8, 2tig+9}.
    u32 Bx[8][2], Bh[8][2];
    float bc0[8], bc1[8];
#pragma unroll
    for (int g = 0; g < 8; ++g) {
        const int n = 8 * g + gid;
        const float sc = (n < 32 || n >= 48) ? 0.5f : 1.0f;
        Bx[g][0] = pkh2(Wi[(2*tig)     * NG + n] * sc, Wi[(2*tig + 1) * NG + n] * sc);
        Bx[g][1] = pkh2(Wi[(2*tig + 8) * NG + n] * sc, Wi[(2*tig + 9) * NG + n] * sc);
        Bh[g][0] = pkh2(Wh[(2*tig)     * NG + n] * sc, Wh[(2*tig + 1) * NG + n] * sc);
        Bh[g][1] = pkh2(Wh[(2*tig + 8) * NG + n] * sc, Wh[(2*tig + 9) * NG + n] * sc);
        const int n0 = 8 * g + 2 * tig;
        bc0[g] = bias[n0]     * sc;
        bc1[g] = bias[n0 + 1] * sc;
    }

    const u32 xbase = smem_u32(&xsm[wib][0][0]);
    const u32 hbase = smem_u32(&hsm[wib][0][0]);
    const u32 laneA = (u32)((gid * RS + 2 * tig) * 4);   // a0 pair; a2 at +32B
    const u32 hwb   = hbase + laneA;                     // h write base (same cols)

    // x fetch roles (lanes 0-15): elem (lane>>1), k-half (lane&1)*8 floats
    const float* xg0 = x + (size_t)(e0 + ((lane >> 1) & 7)) * (NT * ND) + (lane & 1) * 8;
    const u32 xfd = xbase + (u32)((((lane >> 1) & 7) * RS + (lane & 1) * 8) * 4);
    const bool fl = (lane < 16);

    // h(0) = 0 in buffer 0 (lane covers cols {2tig,2tig+1} and {8+2tig,...})
    sts64(hwb + 0,  0.f, 0.f);
    sts64(hwb + 32, 0.f, 0.f);

    // prologue: x(0) -> slot 0, x(1) -> slot 1
    if (fl) { cp16(xfd, xg0); cp16(xfd + 16, xg0 + 4); }
    cp_commit();
    if (fl) { cp16(xfd + SLOT_B, xg0 + ND); cp16(xfd + SLOT_B + 16, xg0 + ND + 4); }
    cp_commit();

    float cst[4];
#pragma unroll
    for (int i = 0; i < 4; ++i) cst[i] = 0.f;

    // one step; s = t & 7. mode: 0 fetch+wait1, 1 wait0, 2 none.
    auto step = [&](int s, int mode, const float* xgp) {
        if (mode == 0) {
            const int ds = (s + 2) & 3;
            if (fl) {
                cp16(xfd + (u32)(ds * SLOT_B),      xgp + s * ND);
                cp16(xfd + (u32)(ds * SLOT_B) + 16, xgp + s * ND + 4);
            }
            cp_commit();
            asm volatile("cp.async.wait_group 1;" ::: "memory");
        } else if (mode == 1) {
            asm volatile("cp.async.wait_group 0;" ::: "memory");
        }
        __syncwarp();

        // A fragments (f32 -> f16x2); rows 8-15 duplicate rows 0-7
        const u32 xb = xbase + (u32)((s & 3) * SLOT_B) + laneA;
        const u32 hb = hbase + (u32)((s & 1) * SLOT_B) + laneA;
        float t0, t1;
        lds64(xb + 0,  t0, t1);  const u32 ax0 = pkh2(t0, t1);
        lds64(xb + 32, t0, t1);  const u32 ax2 = pkh2(t0, t1);
        lds64(hb + 0,  t0, t1);  const u32 ah0 = pkh2(t0, t1);
        lds64(hb + 32, t0, t1);  const u32 ah2 = pkh2(t0, t1);

        // z = x@Wi + h@Wh + b; 2 chained mma per gate-group, keep d0,d1
        float z[8][2];
#pragma unroll
        for (int g = 0; g < 8; ++g) {
            float d0, d1, d2, d3;
            mma16(d0, d1, d2, d3, ax0, ax0, ax2, ax2,
                  Bx[g][0], Bx[g][1], bc0[g], bc1[g], bc0[g], bc1[g]);
            mma16(d0, d1, d2, d3, ah0, ah0, ah2, ah2,
                  Bh[g][0], Bh[g][1], d0, d1, d2, d3);
            z[g][0] = d0; z[g][1] = d1;
        }

        // activations: 4 (e,j) pairs per lane; j = 8*gj + 2*tig + cs
        const u32 hw = hwb + (u32)(((s & 1) ^ 1) * SLOT_B);
        float hv[4];
#pragma unroll
        for (int gj = 0; gj < 2; ++gj)
#pragma unroll
        for (int cs = 0; cs < 2; ++cs) {
            float vI = fmaf(0.5f, tanhap(z[gj    ][cs]), 0.5f);
            float vF = fmaf(0.5f, tanhap(z[gj + 2][cs]), 0.5f);
            float vG = tanhap(z[gj + 4][cs]);
            float vO = fmaf(0.5f, tanhap(z[gj + 6][cs]), 0.5f);
            const int ix = gj * 2 + cs;
            cst[ix] = fmaf(vF, cst[ix], vI * vG);
            hv[ix]  = vO * tanhap(cst[ix]);
        }
        sts64(hw + 0,  hv[0], hv[1]);    // cols 2tig, 2tig+1
        sts64(hw + 32, hv[2], hv[3]);    // cols 8+2tig, 8+2tig+1
    };

    const float* xg = xg0 + 2 * ND;   // source base: x(tb + 2 + s)

#pragma unroll 1
    for (int tb = 0; tb < NT - 8; tb += 8) {
#pragma unroll
        for (int s = 0; s < 8; ++s)
            step(s, 0, xg);
        xg += 8 * ND;
    }
    // final block: fetch while t+2 <= 1023, then drain
#pragma unroll
    for (int s = 0; s < 8; ++s)
        step(s, (s < 6) ? 0 : ((s == 6) ? 1 : 2), xg);

    // ---- head: logits = c_T @ Wd + bd, softmax(2); elem = e0 + gid ----
    float p0 = 0.f, p1 = 0.f;
#pragma unroll
    for (int gj = 0; gj < 2; ++gj)
#pragma unroll
    for (int cs = 0; cs < 2; ++cs) {
        const int jj = 8 * gj + 2 * tig + cs;
        p0 += cst[gj * 2 + cs] * Wd[jj * 2];
        p1 += cst[gj * 2 + cs] * Wd[jj * 2 + 1];
    }
#pragma unroll
    for (int off = 1; off <= 2; off <<= 1) {
        p0 += __shfl_xor_sync(0xffffffffu, p0, off);
        p1 += __shfl_xor_sync(0xffffffffu, p1, off);
    }
    if (tig == 0) {
        const float L2E = 1.44269504088896340736f;
        const int e = e0 + gid;
        float l0 = p0 + bd[0];
        float l1 = p1 + bd[1];
        float mx = fmaxf(l0, l1);
        float q0 = ex2f((l0 - mx) * L2E);
        float q1 = ex2f((l1 - mx) * L2E);
        float inv = rcpf(q0 + q1);
        out[2 * e]     = q0 * inv;
        out[2 * e + 1] = q1 * inv;
    }
}

extern "C" void kernel_launch(void* const* d_in, const int* in_sizes, int n_in,
                              void* d_out, int out_size)
{
    const float* x  = (const float*)d_in[0];
    const float* Wi = (const float*)d_in[1];
    const float* Wh = (const float*)d_in[2];
    const float* b  = (const float*)d_in[3];
    const float* Wd = (const float*)d_in[4];
    const float* bd = (const float*)d_in[5];
    float* out = (float*)d_out;

    lstm_mma_kernel<<<NB / 32, 128>>>(x, Wi, Wh, b, Wd, bd, out);
}